// round 1
// baseline (speedup 1.0000x reference)
#include <cuda_runtime.h>
#include <math.h>

// Shapes (fixed by the problem)
#define B_    2
#define I_    8
#define J_    1025
#define M_    256
#define H_    8
#define DH_   32
#define NSLAB 16              // B_*I_
#define RTOT  (NSLAB * J_)    // 16400
#define FF_   1024            // 4*M

// ---- scratch (static __device__ arrays; no runtime allocation) ----
__device__ float g_sln[RTOT * M_];           // layernorm1(savespace)
__device__ float g_s2 [RTOT * M_];           // s2 = wosum*imv + savespace
__device__ float g_hln[RTOT * M_];           // layernorm2(s2)
__device__ float g_h1 [(size_t)RTOT * FF_];  // gelu(fc1)
__device__ float g_G  [NSLAB * M_ * M_];     // per-slab Gram S^T S
__device__ float g_ET [NSLAB * M_ * M_];     // per-slab E transposed: ET[col][p]
__device__ float g_wosum[M_];

// ============================================================
// LayerNorm over last dim M_=256, one block (256 thr) per row
// ============================================================
__global__ void ln_kernel(const float* __restrict__ x,
                          const float* __restrict__ g,
                          const float* __restrict__ b,
                          float* __restrict__ out)
{
    int row = blockIdx.x;
    const float* xr = x + (size_t)row * M_;
    int t = threadIdx.x;
    float v = xr[t];

    __shared__ float sm[8];
    // mean
    float s = v;
    #pragma unroll
    for (int o = 16; o > 0; o >>= 1) s += __shfl_xor_sync(0xffffffffu, s, o);
    if ((t & 31) == 0) sm[t >> 5] = s;
    __syncthreads();
    float mean = 0.f;
    #pragma unroll
    for (int i = 0; i < 8; i++) mean += sm[i];
    mean *= (1.0f / M_);
    __syncthreads();
    // variance
    float d = v - mean;
    float q = d * d;
    #pragma unroll
    for (int o = 16; o > 0; o >>= 1) q += __shfl_xor_sync(0xffffffffu, q, o);
    if ((t & 31) == 0) sm[t >> 5] = q;
    __syncthreads();
    float var = 0.f;
    #pragma unroll
    for (int i = 0; i < 8; i++) var += sm[i];
    var *= (1.0f / M_);

    out[(size_t)row * M_ + t] = d * rsqrtf(var + 1e-5f) * g[t] + b[t];
}

// ============================================================
// Wo row sums: wosum[n] = sum_m Wo[n,m]
// ============================================================
__global__ void rowsum_kernel(const float* __restrict__ Wo, float* __restrict__ ws)
{
    int n = threadIdx.x;
    float s = 0.f;
    for (int m = 0; m < M_; m++) s += Wo[(size_t)n * M_ + m];
    ws[n] = s;
}

// ============================================================
// Gram: G = S^T S per slab (exploits symmetry: q-tile >= p-tile)
// 64x64 tile, BK=16, 4x4 per thread.
// ============================================================
__global__ void __launch_bounds__(256) gram_kernel(const float* __restrict__ sln,
                                                   float* __restrict__ G)
{
    if (blockIdx.y < blockIdx.x) return;  // symmetry
    int slab = blockIdx.z;
    const float* A = sln + (size_t)slab * J_ * M_;
    int p0 = blockIdx.x * 64, q0 = blockIdx.y * 64;

    __shared__ float As[16][64], Bs[16][64];
    int tid = threadIdx.x;
    int jj = tid >> 4;            // 0..15
    int cq = (tid & 15) << 2;     // 0..60
    int tx = tid & 15, ty = tid >> 4;

    float acc[4][4] = {};
    for (int j0 = 0; j0 < J_; j0 += 16) {
        int j = j0 + jj;
        float4 av, bv;
        if (j < J_) {
            av = *(const float4*)(A + (size_t)j * M_ + p0 + cq);
            bv = *(const float4*)(A + (size_t)j * M_ + q0 + cq);
        } else {
            av = make_float4(0.f, 0.f, 0.f, 0.f);
            bv = av;
        }
        *(float4*)&As[jj][cq] = av;
        *(float4*)&Bs[jj][cq] = bv;
        __syncthreads();
        #pragma unroll
        for (int k = 0; k < 16; k++) {
            float4 a = *(const float4*)&As[k][ty << 2];
            float4 b = *(const float4*)&Bs[k][tx << 2];
            acc[0][0] = fmaf(a.x, b.x, acc[0][0]); acc[0][1] = fmaf(a.x, b.y, acc[0][1]);
            acc[0][2] = fmaf(a.x, b.z, acc[0][2]); acc[0][3] = fmaf(a.x, b.w, acc[0][3]);
            acc[1][0] = fmaf(a.y, b.x, acc[1][0]); acc[1][1] = fmaf(a.y, b.y, acc[1][1]);
            acc[1][2] = fmaf(a.y, b.z, acc[1][2]); acc[1][3] = fmaf(a.y, b.w, acc[1][3]);
            acc[2][0] = fmaf(a.z, b.x, acc[2][0]); acc[2][1] = fmaf(a.z, b.y, acc[2][1]);
            acc[2][2] = fmaf(a.z, b.z, acc[2][2]); acc[2][3] = fmaf(a.z, b.w, acc[2][3]);
            acc[3][0] = fmaf(a.w, b.x, acc[3][0]); acc[3][1] = fmaf(a.w, b.y, acc[3][1]);
            acc[3][2] = fmaf(a.w, b.z, acc[3][2]); acc[3][3] = fmaf(a.w, b.w, acc[3][3]);
        }
        __syncthreads();
    }
    float* Gs = G + (size_t)slab * M_ * M_;
    #pragma unroll
    for (int i = 0; i < 4; i++) {
        int p = p0 + (ty << 2) + i;
        #pragma unroll
        for (int j = 0; j < 4; j++) {
            int q = q0 + (tx << 2) + j;
            Gs[(size_t)p * M_ + q] = acc[i][j];
            Gs[(size_t)q * M_ + p] = acc[i][j];   // mirror
        }
    }
}

// ============================================================
// Assemble ET per (head, slab):
//   A_h  = Wk_h @ G                (32 x 256)
//   KtV  = A_h @ Wv_h^T            (32 x 32)
//   ET[h*32+d][p] = scale * sum_e Wq_h[e][p] * KtV[e][d]
// ============================================================
__global__ void __launch_bounds__(256) assemble_kernel(const float* __restrict__ Wqkv,
                                                       const float* __restrict__ G,
                                                       float* __restrict__ ET)
{
    int h = blockIdx.x;      // 0..7
    int slab = blockIdx.y;   // 0..15
    const float* Gs = G + (size_t)slab * M_ * M_;
    const float* Wq = Wqkv + (size_t)(0 * H_ + h) * DH_ * M_;
    const float* Wk = Wqkv + (size_t)(1 * H_ + h) * DH_ * M_;
    const float* Wv = Wqkv + (size_t)(2 * H_ + h) * DH_ * M_;

    __shared__ float bufA[32 * 256];  // Wk, then reused for A_h
    __shared__ float wvt[32][65];
    __shared__ float ktv[32][33];
    int tid = threadIdx.x;

    for (int i = tid; i < 8192; i += 256) bufA[i] = Wk[i];
    __syncthreads();

    // step 1: per-thread column m=tid of A_h
    float acc[32];
    #pragma unroll
    for (int d = 0; d < 32; d++) acc[d] = 0.f;
    for (int p = 0; p < 256; p++) {
        float gv = Gs[(size_t)p * 256 + tid];
        #pragma unroll
        for (int d = 0; d < 32; d++) acc[d] = fmaf(bufA[d * 256 + p], gv, acc[d]);
    }
    __syncthreads();
    #pragma unroll
    for (int d = 0; d < 32; d++) bufA[d * 256 + tid] = acc[d];
    __syncthreads();

    // step 2: KtV[e][d2]
    int e  = tid >> 3;           // 0..31
    int d2b = (tid & 7) << 2;    // 0,4,...,28
    float k4[4] = {0.f, 0.f, 0.f, 0.f};
    for (int m0 = 0; m0 < 256; m0 += 64) {
        __syncthreads();
        for (int i = tid; i < 2048; i += 256) {
            int d2 = i >> 6, mm = i & 63;
            wvt[d2][mm] = Wv[(size_t)d2 * 256 + m0 + mm];
        }
        __syncthreads();
        for (int mm = 0; mm < 64; mm++) {
            float a = bufA[e * 256 + m0 + mm];
            #pragma unroll
            for (int j = 0; j < 4; j++) k4[j] = fmaf(a, wvt[d2b + j][mm], k4[j]);
        }
    }
    #pragma unroll
    for (int j = 0; j < 4; j++) ktv[e][d2b + j] = k4[j];
    __syncthreads();

    // step 3: ET columns (coalesced writes since ET is transposed)
    float acc3[32];
    #pragma unroll
    for (int d = 0; d < 32; d++) acc3[d] = 0.f;
    for (int e2 = 0; e2 < 32; e2++) {
        float w = Wq[(size_t)e2 * 256 + tid];
        #pragma unroll
        for (int d = 0; d < 32; d++) acc3[d] = fmaf(w, ktv[e2][d], acc3[d]);
    }
    const float scale = 0.17677669529663687f; // 1/sqrt(32)
    float* ETs = ET + (size_t)slab * M_ * M_;
    #pragma unroll
    for (int d = 0; d < 32; d++)
        ETs[(size_t)(h * 32 + d) * 256 + tid] = scale * acc3[d];
}

// ============================================================
// Generic NT GEMM: C[r,c] = sum_k A[r,k] * B[c,k]  (+ epilogue)
//   mode 0: C = acc * e1[c] + e2[r,c]        (s2)
//   mode 1: C = gelu(acc + e1[c])            (fc1)
//   mode 2: C = acc + e1[c] + e2[r,c]        (fc2 + residual)
// 64x64 tile, BK=16, 4x4 per thread, 256 threads.
// ============================================================
__global__ void __launch_bounds__(256) gemm_nt(
    const float* __restrict__ Ab, int lda, long aStride,
    const float* __restrict__ Bb, int ldb, long bStride,
    float* __restrict__ Cb, int ldc, long cStride,
    int K, int Rlim, int mode,
    const float* __restrict__ e1,
    const float* __restrict__ e2, long e2Stride)
{
    int slab = blockIdx.z;
    const float* A = Ab + (size_t)slab * aStride;
    const float* B = Bb + (size_t)slab * bStride;
    float*       C = Cb + (size_t)slab * cStride;
    const float* E2 = e2 ? (e2 + (size_t)slab * e2Stride) : (const float*)0;

    int rowBase = blockIdx.x * 64;
    int colBase = blockIdx.y * 64;

    __shared__ float As[16][64], Bs[16][64];
    int tid = threadIdx.x;
    int lm = tid >> 2;           // 0..63
    int lk = (tid & 3) << 2;     // 0,4,8,12
    int tx = tid & 15, ty = tid >> 4;

    float acc[4][4] = {};
    for (int k0 = 0; k0 < K; k0 += 16) {
        int r = rowBase + lm;
        float4 av = (r < Rlim)
            ? *(const float4*)(A + (size_t)r * lda + k0 + lk)
            : make_float4(0.f, 0.f, 0.f, 0.f);
        As[lk + 0][lm] = av.x; As[lk + 1][lm] = av.y;
        As[lk + 2][lm] = av.z; As[lk + 3][lm] = av.w;

        float4 bv = *(const float4*)(B + (size_t)(colBase + lm) * ldb + k0 + lk);
        Bs[lk + 0][lm] = bv.x; Bs[lk + 1][lm] = bv.y;
        Bs[lk + 2][lm] = bv.z; Bs[lk + 3][lm] = bv.w;
        __syncthreads();
        #pragma unroll
        for (int k = 0; k < 16; k++) {
            float4 a = *(const float4*)&As[k][ty << 2];
            float4 b = *(const float4*)&Bs[k][tx << 2];
            acc[0][0] = fmaf(a.x, b.x, acc[0][0]); acc[0][1] = fmaf(a.x, b.y, acc[0][1]);
            acc[0][2] = fmaf(a.x, b.z, acc[0][2]); acc[0][3] = fmaf(a.x, b.w, acc[0][3]);
            acc[1][0] = fmaf(a.y, b.x, acc[1][0]); acc[1][1] = fmaf(a.y, b.y, acc[1][1]);
            acc[1][2] = fmaf(a.y, b.z, acc[1][2]); acc[1][3] = fmaf(a.y, b.w, acc[1][3]);
            acc[2][0] = fmaf(a.z, b.x, acc[2][0]); acc[2][1] = fmaf(a.z, b.y, acc[2][1]);
            acc[2][2] = fmaf(a.z, b.z, acc[2][2]); acc[2][3] = fmaf(a.z, b.w, acc[2][3]);
            acc[3][0] = fmaf(a.w, b.x, acc[3][0]); acc[3][1] = fmaf(a.w, b.y, acc[3][1]);
            acc[3][2] = fmaf(a.w, b.z, acc[3][2]); acc[3][3] = fmaf(a.w, b.w, acc[3][3]);
        }
        __syncthreads();
    }

    #pragma unroll
    for (int i = 0; i < 4; i++) {
        int r = rowBase + (ty << 2) + i;
        if (r >= Rlim) continue;
        #pragma unroll
        for (int j = 0; j < 4; j++) {
            int c = colBase + (tx << 2) + j;
            float v = acc[i][j];
            size_t idx = (size_t)r * ldc + c;
            if (mode == 0) {
                v = v * e1[c] + E2[idx];
            } else if (mode == 1) {
                v += e1[c];
                v = 0.5f * v * (1.0f + erff(v * 0.7071067811865475f));
            } else {
                v = v + e1[c] + E2[idx];
            }
            C[idx] = v;
        }
    }
}

// ============================================================
// Launch
// ============================================================
extern "C" void kernel_launch(void* const* d_in, const int* in_sizes, int n_in,
                              void* d_out, int out_size)
{
    (void)in_sizes; (void)n_in; (void)out_size;
    const float* savespace = (const float*)d_in[1];
    const float* Wqkv      = (const float*)d_in[2];
    const float* Wo        = (const float*)d_in[3];
    const float* ln1_g     = (const float*)d_in[4];
    const float* ln1_b     = (const float*)d_in[5];
    const float* ln2_g     = (const float*)d_in[6];
    const float* ln2_b     = (const float*)d_in[7];
    const float* fc1_w     = (const float*)d_in[8];
    const float* fc1_b     = (const float*)d_in[9];
    const float* fc2_w     = (const float*)d_in[10];
    const float* fc2_b     = (const float*)d_in[11];
    float* out = (float*)d_out;

    float *p_sln, *p_s2, *p_hln, *p_h1, *p_G, *p_ET, *p_ws;
    cudaGetSymbolAddress((void**)&p_sln, g_sln);
    cudaGetSymbolAddress((void**)&p_s2,  g_s2);
    cudaGetSymbolAddress((void**)&p_hln, g_hln);
    cudaGetSymbolAddress((void**)&p_h1,  g_h1);
    cudaGetSymbolAddress((void**)&p_G,   g_G);
    cudaGetSymbolAddress((void**)&p_ET,  g_ET);
    cudaGetSymbolAddress((void**)&p_ws,  g_wosum);

    const long SLAB = (long)J_ * M_;       // 262400
    const long EST  = (long)M_ * M_;       // 65536

    // 1) layernorm1
    ln_kernel<<<RTOT, 256>>>(savespace, ln1_g, ln1_b, p_sln);
    // 2) Gram per slab
    gram_kernel<<<dim3(4, 4, NSLAB), 256>>>(p_sln, p_G);
    // 3) Wo row sums
    rowsum_kernel<<<1, 256>>>(Wo, p_ws);
    // 4) assemble ET per (head, slab)
    assemble_kernel<<<dim3(H_, NSLAB), 256>>>(Wqkv, p_G, p_ET);
    // 5) s2 = wosum * (s_ln @ E) + savespace
    gemm_nt<<<dim3(17, 4, NSLAB), 256>>>(
        p_sln, M_, SLAB,  p_ET, M_, EST,  p_s2, M_, SLAB,
        M_, J_, 0, p_ws, savespace, SLAB);
    // 6) layernorm2
    ln_kernel<<<RTOT, 256>>>(p_s2, ln2_g, ln2_b, p_hln);
    // 7) h1 = gelu(hln @ fc1_w^T + b1)
    gemm_nt<<<dim3(257, 16, 1), 256>>>(
        p_hln, M_, 0,  fc1_w, M_, 0,  p_h1, FF_, 0,
        M_, RTOT, 1, fc1_b, (const float*)0, 0);
    // 8) out = h1 @ fc2_w^T + b2 + s2
    gemm_nt<<<dim3(257, 4, 1), 256>>>(
        p_h1, FF_, 0,  fc2_w, FF_, 0,  out, M_, 0,
        FF_, RTOT, 2, fc2_b, p_s2, 0);
}

// round 3
// speedup vs baseline: 1.3757x; 1.3757x over previous
#include <cuda_runtime.h>
#include <math.h>

// Shapes (fixed by the problem)
#define B_    2
#define I_    8
#define J_    1025
#define M_    256
#define H_    8
#define DH_   32
#define NSLAB 16              // B_*I_
#define RTOT  (NSLAB * J_)    // 16400
#define FF_   1024            // 4*M

typedef unsigned long long u64;

// ---- scratch (static __device__ arrays; no runtime allocation) ----
__device__ float g_sln[RTOT * M_];           // layernorm1(savespace)
__device__ float g_s2 [RTOT * M_];           // s2 = wosum*imv + savespace
__device__ float g_hln[RTOT * M_];           // layernorm2(s2)
__device__ float g_h1 [(size_t)RTOT * FF_];  // gelu(fc1)
__device__ float g_G  [NSLAB * M_ * M_];     // per-slab Gram S^T S
__device__ float g_T  [NSLAB * M_ * M_];     // T = G @ Wv_full^T per slab
__device__ float g_ET [NSLAB * M_ * M_];     // per-slab E transposed: ET[col][p]
__device__ float g_wosum[M_];

// ---- f32x2 packed-FMA helpers ----
__device__ __forceinline__ u64 dup2(float x) {
    u64 r; asm("mov.b64 %0, {%1,%1};" : "=l"(r) : "f"(x)); return r;
}
__device__ __forceinline__ void fma2(u64& d, u64 a, u64 b) {
    asm("fma.rn.f32x2 %0, %1, %2, %0;" : "+l"(d) : "l"(a), "l"(b));
}
__device__ __forceinline__ float2 unpack2(u64 v) {
    float2 r; asm("mov.b64 {%0,%1}, %2;" : "=f"(r.x), "=f"(r.y) : "l"(v)); return r;
}

// ============================================================
// LayerNorm over last dim M_=256, one block (256 thr) per row
// ============================================================
__global__ void ln_kernel(const float* __restrict__ x,
                          const float* __restrict__ g,
                          const float* __restrict__ b,
                          float* __restrict__ out)
{
    int row = blockIdx.x;
    const float* xr = x + (size_t)row * M_;
    int t = threadIdx.x;
    float v = xr[t];

    __shared__ float sm[8];
    float s = v;
    #pragma unroll
    for (int o = 16; o > 0; o >>= 1) s += __shfl_xor_sync(0xffffffffu, s, o);
    if ((t & 31) == 0) sm[t >> 5] = s;
    __syncthreads();
    float mean = 0.f;
    #pragma unroll
    for (int i = 0; i < 8; i++) mean += sm[i];
    mean *= (1.0f / M_);
    __syncthreads();
    float d = v - mean;
    float q = d * d;
    #pragma unroll
    for (int o = 16; o > 0; o >>= 1) q += __shfl_xor_sync(0xffffffffu, q, o);
    if ((t & 31) == 0) sm[t >> 5] = q;
    __syncthreads();
    float var = 0.f;
    #pragma unroll
    for (int i = 0; i < 8; i++) var += sm[i];
    var *= (1.0f / M_);

    out[(size_t)row * M_ + t] = d * rsqrtf(var + 1e-5f) * g[t] + b[t];
}

// ============================================================
// Wo row sums
// ============================================================
__global__ void rowsum_kernel(const float* __restrict__ Wo, float* __restrict__ ws)
{
    int n = threadIdx.x;
    float s = 0.f;
    for (int m = 0; m < M_; m++) s += Wo[(size_t)n * M_ + m];
    ws[n] = s;
}

// ============================================================
// Gram: G = S^T S per slab, symmetry-exploiting, f32x2 inner
// 64x64 tile, BK=16, 4x4 per thread.
// ============================================================
__global__ void __launch_bounds__(256) gram_kernel(const float* __restrict__ sln,
                                                   float* __restrict__ G)
{
    if (blockIdx.y < blockIdx.x) return;
    int slab = blockIdx.z;
    const float* A = sln + (size_t)slab * J_ * M_;
    int p0 = blockIdx.x * 64, q0 = blockIdx.y * 64;

    __shared__ float As[16][64], Bs[16][64];
    int tid = threadIdx.x;
    int jj = tid >> 4;
    int cq = (tid & 15) << 2;
    int tx = tid & 15, ty = tid >> 4;

    u64 acc[4][2] = {};
    for (int j0 = 0; j0 < J_; j0 += 16) {
        int j = j0 + jj;
        float4 av, bv;
        if (j < J_) {
            av = *(const float4*)(A + (size_t)j * M_ + p0 + cq);
            bv = *(const float4*)(A + (size_t)j * M_ + q0 + cq);
        } else {
            av = make_float4(0.f, 0.f, 0.f, 0.f);
            bv = av;
        }
        *(float4*)&As[jj][cq] = av;
        *(float4*)&Bs[jj][cq] = bv;
        __syncthreads();
        #pragma unroll
        for (int k = 0; k < 16; k++) {
            float4 a = *(const float4*)&As[k][ty << 2];
            ulonglong2 b = *(const ulonglong2*)&Bs[k][tx << 2];
            u64 a2;
            a2 = dup2(a.x); fma2(acc[0][0], a2, b.x); fma2(acc[0][1], a2, b.y);
            a2 = dup2(a.y); fma2(acc[1][0], a2, b.x); fma2(acc[1][1], a2, b.y);
            a2 = dup2(a.z); fma2(acc[2][0], a2, b.x); fma2(acc[2][1], a2, b.y);
            a2 = dup2(a.w); fma2(acc[3][0], a2, b.x); fma2(acc[3][1], a2, b.y);
        }
        __syncthreads();
    }
    float* Gs = G + (size_t)slab * M_ * M_;
    #pragma unroll
    for (int i = 0; i < 4; i++) {
        int p = p0 + (ty << 2) + i;
        #pragma unroll
        for (int j2 = 0; j2 < 2; j2++) {
            float2 v = unpack2(acc[i][j2]);
            int q = q0 + (tx << 2) + j2 * 2;
            Gs[(size_t)p * M_ + q]     = v.x;
            Gs[(size_t)p * M_ + q + 1] = v.y;
            Gs[(size_t)q * M_ + p]       = v.x;
            Gs[(size_t)(q + 1) * M_ + p] = v.y;
        }
    }
}

// ============================================================
// 64x64 NT GEMM (used for T = G @ Wv^T, plain store)
// ============================================================
__global__ void __launch_bounds__(256) gemm64(
    const float* __restrict__ Ab, int lda, long aStride,
    const float* __restrict__ Bb, int ldb, long bStride,
    float* __restrict__ Cb, int ldc, long cStride, int K)
{
    int slab = blockIdx.z;
    const float* A = Ab + (size_t)slab * aStride;
    const float* B = Bb + (size_t)slab * bStride;
    float*       C = Cb + (size_t)slab * cStride;

    int rowBase = blockIdx.x * 64;
    int colBase = blockIdx.y * 64;

    __shared__ float As[16][64], Bs[16][64];
    int tid = threadIdx.x;
    int lm = tid >> 2;
    int lk = (tid & 3) << 2;
    int tx = tid & 15, ty = tid >> 4;

    u64 acc[4][2] = {};
    for (int k0 = 0; k0 < K; k0 += 16) {
        float4 av = *(const float4*)(A + (size_t)(rowBase + lm) * lda + k0 + lk);
        As[lk + 0][lm] = av.x; As[lk + 1][lm] = av.y;
        As[lk + 2][lm] = av.z; As[lk + 3][lm] = av.w;
        float4 bv = *(const float4*)(B + (size_t)(colBase + lm) * ldb + k0 + lk);
        Bs[lk + 0][lm] = bv.x; Bs[lk + 1][lm] = bv.y;
        Bs[lk + 2][lm] = bv.z; Bs[lk + 3][lm] = bv.w;
        __syncthreads();
        #pragma unroll
        for (int k = 0; k < 16; k++) {
            float4 a = *(const float4*)&As[k][ty << 2];
            ulonglong2 b = *(const ulonglong2*)&Bs[k][tx << 2];
            u64 a2;
            a2 = dup2(a.x); fma2(acc[0][0], a2, b.x); fma2(acc[0][1], a2, b.y);
            a2 = dup2(a.y); fma2(acc[1][0], a2, b.x); fma2(acc[1][1], a2, b.y);
            a2 = dup2(a.z); fma2(acc[2][0], a2, b.x); fma2(acc[2][1], a2, b.y);
            a2 = dup2(a.w); fma2(acc[3][0], a2, b.x); fma2(acc[3][1], a2, b.y);
        }
        __syncthreads();
    }
    #pragma unroll
    for (int i = 0; i < 4; i++) {
        int r = rowBase + (ty << 2) + i;
        #pragma unroll
        for (int j2 = 0; j2 < 2; j2++) {
            int c = colBase + (tx << 2) + j2 * 2;
            float2 v = unpack2(acc[i][j2]);
            *(float2*)(C + (size_t)r * ldc + c) = v;
        }
    }
}

// ============================================================
// Small per-(head,slab) finisher:
//   KtV[e][d] = sum_m Wk_h[e][m] * T[slab][m][h*32+d]
//   ET[h*32+d][p] = scale * sum_e Wq_h[e][p] * KtV[e][d]
// ============================================================
__global__ void __launch_bounds__(256) assemble2_kernel(const float* __restrict__ Wqkv,
                                                        const float* __restrict__ T,
                                                        float* __restrict__ ET)
{
    int h = blockIdx.x;
    int slab = blockIdx.y;
    const float* Ts = T + (size_t)slab * M_ * M_;
    const float* Wq = Wqkv + (size_t)(0 * H_ + h) * DH_ * M_;
    const float* Wk = Wqkv + (size_t)(1 * H_ + h) * DH_ * M_;

    __shared__ float sT[256][33];
    __shared__ float ktv[32][33];
    int tid = threadIdx.x;

    // stage T slice [256 m][32 d] (coalesced 32-float rows)
    {
        int m = tid >> 5, d = tid & 31;   // 8 m-rows per pass
        #pragma unroll
        for (int pass = 0; pass < 32; pass++) {
            int mm = pass * 8 + m;
            sT[mm][d] = Ts[(size_t)mm * M_ + h * 32 + d];
        }
    }
    __syncthreads();

    // KtV: each thread computes 4 e-values for its d column.
    // (32 e) x (32 d) = 1024 entries / 256 threads = 4 per thread.
    {
        int d  = tid & 31;
        int e0 = (tid >> 5) << 2;    // 0,4,...,28
        float acc4[4] = {0.f, 0.f, 0.f, 0.f};
        for (int m = 0; m < 256; m++) {
            float t = sT[m][d];
            #pragma unroll
            for (int ee = 0; ee < 4; ee++)
                acc4[ee] = fmaf(Wk[(size_t)(e0 + ee) * M_ + m], t, acc4[ee]);
        }
        #pragma unroll
        for (int ee = 0; ee < 4; ee++)
            ktv[e0 + ee][d] = acc4[ee];
    }
    __syncthreads();

    // ET: thread = column p
    float acc3[32];
    #pragma unroll
    for (int d = 0; d < 32; d++) acc3[d] = 0.f;
    for (int e2 = 0; e2 < 32; e2++) {
        float w = Wq[(size_t)e2 * M_ + tid];
        #pragma unroll
        for (int d = 0; d < 32; d++) acc3[d] = fmaf(w, ktv[e2][d], acc3[d]);
    }
    const float scale = 0.17677669529663687f; // 1/sqrt(32)
    float* ETs = ET + (size_t)slab * M_ * M_;
    #pragma unroll
    for (int d = 0; d < 32; d++)
        ETs[(size_t)(h * 32 + d) * M_ + tid] = scale * acc3[d];
}

// ============================================================
// 128x128 NT GEMM with f32x2, 8x8 per thread, 256 threads.
//   C[r,c] = sum_k A[r,k] * B[c,k]  (+ epilogue)
//   mode 0: C = acc * e1[c] + e2[r,c]        (s2)
//   mode 1: C = gelu(acc + e1[c])            (fc1)
//   mode 2: C = acc + e1[c] + e2[r,c]        (fc2 + residual)
// Columns must be a multiple of 128; rows guarded by Rlim.
// ============================================================
__global__ void __launch_bounds__(256) gemm128(
    const float* __restrict__ Ab, int lda, long aStride,
    const float* __restrict__ Bb, int ldb, long bStride,
    float* __restrict__ Cb, int ldc, long cStride,
    int K, int Rlim, int mode,
    const float* __restrict__ e1,
    const float* __restrict__ e2, long e2Stride)
{
    int slab = blockIdx.z;
    const float* A = Ab + (size_t)slab * aStride;
    const float* B = Bb + (size_t)slab * bStride;
    float*       C = Cb + (size_t)slab * cStride;
    const float* E2 = e2 ? (e2 + (size_t)slab * e2Stride) : (const float*)0;

    int rowBase = blockIdx.x * 128;
    int colBase = blockIdx.y * 128;

    __shared__ float As[16][128], Bs[16][128];
    int tid = threadIdx.x;
    int ldRow = tid >> 1;            // 0..127
    int ldK   = (tid & 1) << 3;      // 0 or 8
    int tx = tid & 15, ty = tid >> 4;
    int tx4 = tx << 2, ty4 = ty << 2;

    const float* Arow = A + (size_t)(rowBase + ldRow) * lda + ldK;
    const float* Brow = B + (size_t)(colBase + ldRow) * ldb + ldK;
    bool aValid = (rowBase + ldRow) < Rlim;

    u64 acc[8][4] = {};
    for (int k0 = 0; k0 < K; k0 += 16) {
        float4 av0, av1;
        if (aValid) {
            av0 = *(const float4*)(Arow + k0);
            av1 = *(const float4*)(Arow + k0 + 4);
        } else {
            av0 = make_float4(0.f, 0.f, 0.f, 0.f);
            av1 = av0;
        }
        float4 bv0 = *(const float4*)(Brow + k0);
        float4 bv1 = *(const float4*)(Brow + k0 + 4);

        As[ldK + 0][ldRow] = av0.x; As[ldK + 1][ldRow] = av0.y;
        As[ldK + 2][ldRow] = av0.z; As[ldK + 3][ldRow] = av0.w;
        As[ldK + 4][ldRow] = av1.x; As[ldK + 5][ldRow] = av1.y;
        As[ldK + 6][ldRow] = av1.z; As[ldK + 7][ldRow] = av1.w;
        Bs[ldK + 0][ldRow] = bv0.x; Bs[ldK + 1][ldRow] = bv0.y;
        Bs[ldK + 2][ldRow] = bv0.z; Bs[ldK + 3][ldRow] = bv0.w;
        Bs[ldK + 4][ldRow] = bv1.x; Bs[ldK + 5][ldRow] = bv1.y;
        Bs[ldK + 6][ldRow] = bv1.z; Bs[ldK + 7][ldRow] = bv1.w;
        __syncthreads();

        #pragma unroll
        for (int k = 0; k < 16; k++) {
            float4 a0 = *(const float4*)&As[k][ty4];
            float4 a1 = *(const float4*)&As[k][ty4 + 64];
            ulonglong2 b0 = *(const ulonglong2*)&Bs[k][tx4];
            ulonglong2 b1 = *(const ulonglong2*)&Bs[k][tx4 + 64];
            u64 a2;
            a2 = dup2(a0.x); fma2(acc[0][0],a2,b0.x); fma2(acc[0][1],a2,b0.y); fma2(acc[0][2],a2,b1.x); fma2(acc[0][3],a2,b1.y);
            a2 = dup2(a0.y); fma2(acc[1][0],a2,b0.x); fma2(acc[1][1],a2,b0.y); fma2(acc[1][2],a2,b1.x); fma2(acc[1][3],a2,b1.y);
            a2 = dup2(a0.z); fma2(acc[2][0],a2,b0.x); fma2(acc[2][1],a2,b0.y); fma2(acc[2][2],a2,b1.x); fma2(acc[2][3],a2,b1.y);
            a2 = dup2(a0.w); fma2(acc[3][0],a2,b0.x); fma2(acc[3][1],a2,b0.y); fma2(acc[3][2],a2,b1.x); fma2(acc[3][3],a2,b1.y);
            a2 = dup2(a1.x); fma2(acc[4][0],a2,b0.x); fma2(acc[4][1],a2,b0.y); fma2(acc[4][2],a2,b1.x); fma2(acc[4][3],a2,b1.y);
            a2 = dup2(a1.y); fma2(acc[5][0],a2,b0.x); fma2(acc[5][1],a2,b0.y); fma2(acc[5][2],a2,b1.x); fma2(acc[5][3],a2,b1.y);
            a2 = dup2(a1.z); fma2(acc[6][0],a2,b0.x); fma2(acc[6][1],a2,b0.y); fma2(acc[6][2],a2,b1.x); fma2(acc[6][3],a2,b1.y);
            a2 = dup2(a1.w); fma2(acc[7][0],a2,b0.x); fma2(acc[7][1],a2,b0.y); fma2(acc[7][2],a2,b1.x); fma2(acc[7][3],a2,b1.y);
        }
        __syncthreads();
    }

    #pragma unroll
    for (int i = 0; i < 8; i++) {
        int r = rowBase + ty4 + (i & 3) + ((i >> 2) << 6);
        if (r >= Rlim) continue;
        #pragma unroll
        for (int j2 = 0; j2 < 4; j2++) {
            int c = colBase + tx4 + ((j2 & 1) << 1) + ((j2 >> 1) << 6);
            float2 v = unpack2(acc[i][j2]);
            size_t idx = (size_t)r * ldc + c;
            if (mode == 0) {
                v.x = v.x * e1[c]     + E2[idx];
                v.y = v.y * e1[c + 1] + E2[idx + 1];
            } else if (mode == 1) {
                v.x += e1[c];
                v.y += e1[c + 1];
                v.x = 0.5f * v.x * (1.0f + erff(v.x * 0.7071067811865475f));
                v.y = 0.5f * v.y * (1.0f + erff(v.y * 0.7071067811865475f));
            } else {
                v.x = v.x + e1[c]     + E2[idx];
                v.y = v.y + e1[c + 1] + E2[idx + 1];
            }
            *(float2*)(C + idx) = v;
        }
    }
}

// ============================================================
// Launch
// ============================================================
extern "C" void kernel_launch(void* const* d_in, const int* in_sizes, int n_in,
                              void* d_out, int out_size)
{
    (void)in_sizes; (void)n_in; (void)out_size;
    const float* savespace = (const float*)d_in[1];
    const float* Wqkv      = (const float*)d_in[2];
    const float* Wo        = (const float*)d_in[3];
    const float* ln1_g     = (const float*)d_in[4];
    const float* ln1_b     = (const float*)d_in[5];
    const float* ln2_g     = (const float*)d_in[6];
    const float* ln2_b     = (const float*)d_in[7];
    const float* fc1_w     = (const float*)d_in[8];
    const float* fc1_b     = (const float*)d_in[9];
    const float* fc2_w     = (const float*)d_in[10];
    const float* fc2_b     = (const float*)d_in[11];
    float* out = (float*)d_out;

    float *p_sln, *p_s2, *p_hln, *p_h1, *p_G, *p_T, *p_ET, *p_ws;
    cudaGetSymbolAddress((void**)&p_sln, g_sln);
    cudaGetSymbolAddress((void**)&p_s2,  g_s2);
    cudaGetSymbolAddress((void**)&p_hln, g_hln);
    cudaGetSymbolAddress((void**)&p_h1,  g_h1);
    cudaGetSymbolAddress((void**)&p_G,   g_G);
    cudaGetSymbolAddress((void**)&p_T,   g_T);
    cudaGetSymbolAddress((void**)&p_ET,  g_ET);
    cudaGetSymbolAddress((void**)&p_ws,  g_wosum);

    const long SLAB = (long)J_ * M_;       // 262400
    const long MM   = (long)M_ * M_;       // 65536

    // 1) layernorm1
    ln_kernel<<<RTOT, 256>>>(savespace, ln1_g, ln1_b, p_sln);
    // 2) Gram per slab
    gram_kernel<<<dim3(4, 4, NSLAB), 256>>>(p_sln, p_G);
    // 3) Wo row sums
    rowsum_kernel<<<1, 256>>>(Wo, p_ws);
    // 4) T = G @ Wv_full^T per slab
    gemm64<<<dim3(4, 4, NSLAB), 256>>>(
        p_G, M_, MM,  Wqkv + 2 * H_ * DH_ * M_, M_, 0,  p_T, M_, MM, M_);
    // 5) finish ET per (head, slab)
    assemble2_kernel<<<dim3(H_, NSLAB), 256>>>(Wqkv, p_T, p_ET);
    // 6) s2 = wosum * (s_ln @ E) + savespace
    gemm128<<<dim3(9, 2, NSLAB), 256>>>(
        p_sln, M_, SLAB,  p_ET, M_, MM,  p_s2, M_, SLAB,
        M_, J_, 0, p_ws, savespace, SLAB);
    // 7) layernorm2
    ln_kernel<<<RTOT, 256>>>(p_s2, ln2_g, ln2_b, p_hln);
    // 8) h1 = gelu(hln @ fc1_w^T + b1)
    gemm128<<<dim3(129, 8, 1), 256>>>(
        p_hln, M_, 0,  fc1_w, M_, 0,  p_h1, FF_, 0,
        M_, RTOT, 1, fc1_b, (const float*)0, 0);
    // 9) out = h1 @ fc2_w^T + b2 + s2
    gemm128<<<dim3(129, 2, 1), 256>>>(
        p_h1, FF_, 0,  fc2_w, FF_, 0,  out, M_, 0,
        FF_, RTOT, 2, fc2_b, p_s2, 0);
}

// round 5
// speedup vs baseline: 1.4261x; 1.0366x over previous
#include <cuda_runtime.h>
#include <math.h>

// Shapes (fixed by the problem)
#define B_    2
#define I_    8
#define J_    1025
#define M_    256
#define H_    8
#define DH_   32
#define NSLAB 16              // B_*I_
#define RTOT  (NSLAB * J_)    // 16400
#define FF_   1024            // 4*M

typedef unsigned long long u64;

// ---- scratch (static __device__ arrays; no runtime allocation) ----
__device__ float g_sln[RTOT * M_];
__device__ float g_s2 [RTOT * M_];
__device__ float g_hln[RTOT * M_];
__device__ float g_h1 [(size_t)RTOT * FF_];
__device__ float g_G  [NSLAB * M_ * M_];
__device__ float g_T  [NSLAB * M_ * M_];
__device__ float g_ET [NSLAB * M_ * M_];
__device__ float g_wosum[M_];

// ---- f32x2 packed-FMA helpers ----
__device__ __forceinline__ u64 dup2(float x) {
    u64 r; asm("mov.b64 %0, {%1,%1};" : "=l"(r) : "f"(x)); return r;
}
__device__ __forceinline__ void fma2(u64& d, u64 a, u64 b) {
    asm("fma.rn.f32x2 %0, %1, %2, %0;" : "+l"(d) : "l"(a), "l"(b));
}
__device__ __forceinline__ float2 unpack2(u64 v) {
    float2 r; asm("mov.b64 {%0,%1}, %2;" : "=f"(r.x), "=f"(r.y) : "l"(v)); return r;
}

// ============================================================
// LayerNorm over last dim M_=256, one block (256 thr) per row
// ============================================================
__global__ void ln_kernel(const float* __restrict__ x,
                          const float* __restrict__ g,
                          const float* __restrict__ b,
                          float* __restrict__ out)
{
    int row = blockIdx.x;
    const float* xr = x + (size_t)row * M_;
    int t = threadIdx.x;
    float v = xr[t];

    __shared__ float sm[8];
    float s = v;
    #pragma unroll
    for (int o = 16; o > 0; o >>= 1) s += __shfl_xor_sync(0xffffffffu, s, o);
    if ((t & 31) == 0) sm[t >> 5] = s;
    __syncthreads();
    float mean = 0.f;
    #pragma unroll
    for (int i = 0; i < 8; i++) mean += sm[i];
    mean *= (1.0f / M_);
    __syncthreads();
    float d = v - mean;
    float q = d * d;
    #pragma unroll
    for (int o = 16; o > 0; o >>= 1) q += __shfl_xor_sync(0xffffffffu, q, o);
    if ((t & 31) == 0) sm[t >> 5] = q;
    __syncthreads();
    float var = 0.f;
    #pragma unroll
    for (int i = 0; i < 8; i++) var += sm[i];
    var *= (1.0f / M_);

    out[(size_t)row * M_ + t] = d * rsqrtf(var + 1e-5f) * g[t] + b[t];
}

// ============================================================
// Wo row sums
// ============================================================
__global__ void rowsum_kernel(const float* __restrict__ Wo, float* __restrict__ ws)
{
    int n = threadIdx.x;
    float s = 0.f;
    for (int m = 0; m < M_; m++) s += Wo[(size_t)n * M_ + m];
    ws[n] = s;
}

// ============================================================
// Gram: G = S^T S per slab, symmetry + f32x2 + double buffer
// 64x64 tile, BK=16, 4x4 per thread.
// ============================================================
__global__ void __launch_bounds__(256) gram_kernel(const float* __restrict__ sln,
                                                   float* __restrict__ G)
{
    if (blockIdx.y < blockIdx.x) return;
    int slab = blockIdx.z;
    const float* A = sln + (size_t)slab * J_ * M_;
    int p0 = blockIdx.x * 64, q0 = blockIdx.y * 64;

    __shared__ float As[2][16][64], Bs[2][16][64];
    int tid = threadIdx.x;
    int jj = tid >> 4;
    int cq = (tid & 15) << 2;
    int tx = tid & 15, ty = tid >> 4;

    const int NT = (J_ + 15) / 16;   // 65

    float4 av, bv;
    {
        int j = jj;   // tile 0
        if (j < J_) {
            av = *(const float4*)(A + (size_t)j * M_ + p0 + cq);
            bv = *(const float4*)(A + (size_t)j * M_ + q0 + cq);
        } else { av = make_float4(0.f,0.f,0.f,0.f); bv = av; }
    }
    *(float4*)&As[0][jj][cq] = av;
    *(float4*)&Bs[0][jj][cq] = bv;
    __syncthreads();

    u64 acc[4][2] = {};
    for (int it = 0; it < NT; it++) {
        int cur = it & 1;
        float4 nav, nbv;
        bool more = (it + 1 < NT);
        if (more) {
            int j = (it + 1) * 16 + jj;
            if (j < J_) {
                nav = *(const float4*)(A + (size_t)j * M_ + p0 + cq);
                nbv = *(const float4*)(A + (size_t)j * M_ + q0 + cq);
            } else { nav = make_float4(0.f,0.f,0.f,0.f); nbv = nav; }
        }
        #pragma unroll
        for (int k = 0; k < 16; k++) {
            float4 a = *(const float4*)&As[cur][k][ty << 2];
            ulonglong2 b = *(const ulonglong2*)&Bs[cur][k][tx << 2];
            u64 a2;
            a2 = dup2(a.x); fma2(acc[0][0], a2, b.x); fma2(acc[0][1], a2, b.y);
            a2 = dup2(a.y); fma2(acc[1][0], a2, b.x); fma2(acc[1][1], a2, b.y);
            a2 = dup2(a.z); fma2(acc[2][0], a2, b.x); fma2(acc[2][1], a2, b.y);
            a2 = dup2(a.w); fma2(acc[3][0], a2, b.x); fma2(acc[3][1], a2, b.y);
        }
        if (more) {
            *(float4*)&As[cur ^ 1][jj][cq] = nav;
            *(float4*)&Bs[cur ^ 1][jj][cq] = nbv;
        }
        __syncthreads();
    }
    float* Gs = G + (size_t)slab * M_ * M_;
    #pragma unroll
    for (int i = 0; i < 4; i++) {
        int p = p0 + (ty << 2) + i;
        #pragma unroll
        for (int j2 = 0; j2 < 2; j2++) {
            float2 v = unpack2(acc[i][j2]);
            int q = q0 + (tx << 2) + j2 * 2;
            Gs[(size_t)p * M_ + q]     = v.x;
            Gs[(size_t)p * M_ + q + 1] = v.y;
            Gs[(size_t)q * M_ + p]       = v.x;
            Gs[(size_t)(q + 1) * M_ + p] = v.y;
        }
    }
}

// ============================================================
// 64x64 NT GEMM (T = G @ Wv^T)
// ============================================================
__global__ void __launch_bounds__(256) gemm64(
    const float* __restrict__ Ab, int lda, long aStride,
    const float* __restrict__ Bb, int ldb, long bStride,
    float* __restrict__ Cb, int ldc, long cStride, int K)
{
    int slab = blockIdx.z;
    const float* A = Ab + (size_t)slab * aStride;
    const float* B = Bb + (size_t)slab * bStride;
    float*       C = Cb + (size_t)slab * cStride;

    int rowBase = blockIdx.x * 64;
    int colBase = blockIdx.y * 64;

    __shared__ float As[16][64], Bs[16][64];
    int tid = threadIdx.x;
    int lm = tid >> 2;
    int lk = (tid & 3) << 2;
    int tx = tid & 15, ty = tid >> 4;

    u64 acc[4][2] = {};
    for (int k0 = 0; k0 < K; k0 += 16) {
        float4 av = *(const float4*)(A + (size_t)(rowBase + lm) * lda + k0 + lk);
        As[lk + 0][lm] = av.x; As[lk + 1][lm] = av.y;
        As[lk + 2][lm] = av.z; As[lk + 3][lm] = av.w;
        float4 bv = *(const float4*)(B + (size_t)(colBase + lm) * ldb + k0 + lk);
        Bs[lk + 0][lm] = bv.x; Bs[lk + 1][lm] = bv.y;
        Bs[lk + 2][lm] = bv.z; Bs[lk + 3][lm] = bv.w;
        __syncthreads();
        #pragma unroll
        for (int k = 0; k < 16; k++) {
            float4 a = *(const float4*)&As[k][ty << 2];
            ulonglong2 b = *(const ulonglong2*)&Bs[k][tx << 2];
            u64 a2;
            a2 = dup2(a.x); fma2(acc[0][0], a2, b.x); fma2(acc[0][1], a2, b.y);
            a2 = dup2(a.y); fma2(acc[1][0], a2, b.x); fma2(acc[1][1], a2, b.y);
            a2 = dup2(a.z); fma2(acc[2][0], a2, b.x); fma2(acc[2][1], a2, b.y);
            a2 = dup2(a.w); fma2(acc[3][0], a2, b.x); fma2(acc[3][1], a2, b.y);
        }
        __syncthreads();
    }
    #pragma unroll
    for (int i = 0; i < 4; i++) {
        int r = rowBase + (ty << 2) + i;
        #pragma unroll
        for (int j2 = 0; j2 < 2; j2++) {
            int c = colBase + (tx << 2) + j2 * 2;
            float2 v = unpack2(acc[i][j2]);
            *(float2*)(C + (size_t)r * ldc + c) = v;
        }
    }
}

// ============================================================
// Small per-(head,slab) finisher
// ============================================================
__global__ void __launch_bounds__(256) assemble2_kernel(const float* __restrict__ Wqkv,
                                                        const float* __restrict__ T,
                                                        float* __restrict__ ET)
{
    int h = blockIdx.x;
    int slab = blockIdx.y;
    const float* Ts = T + (size_t)slab * M_ * M_;
    const float* Wq = Wqkv + (size_t)(0 * H_ + h) * DH_ * M_;
    const float* Wk = Wqkv + (size_t)(1 * H_ + h) * DH_ * M_;

    __shared__ float sT[256][33];
    __shared__ float ktv[32][33];
    int tid = threadIdx.x;

    {
        int m = tid >> 5, d = tid & 31;
        #pragma unroll
        for (int pass = 0; pass < 32; pass++) {
            int mm = pass * 8 + m;
            sT[mm][d] = Ts[(size_t)mm * M_ + h * 32 + d];
        }
    }
    __syncthreads();

    {
        int d  = tid & 31;
        int e0 = (tid >> 5) << 2;
        float acc4[4] = {0.f, 0.f, 0.f, 0.f};
        for (int m = 0; m < 256; m++) {
            float t = sT[m][d];
            #pragma unroll
            for (int ee = 0; ee < 4; ee++)
                acc4[ee] = fmaf(Wk[(size_t)(e0 + ee) * M_ + m], t, acc4[ee]);
        }
        #pragma unroll
        for (int ee = 0; ee < 4; ee++)
            ktv[e0 + ee][d] = acc4[ee];
    }
    __syncthreads();

    float acc3[32];
    #pragma unroll
    for (int d = 0; d < 32; d++) acc3[d] = 0.f;
    for (int e2 = 0; e2 < 32; e2++) {
        float w = Wq[(size_t)e2 * M_ + tid];
        #pragma unroll
        for (int d = 0; d < 32; d++) acc3[d] = fmaf(w, ktv[e2][d], acc3[d]);
    }
    const float scale = 0.17677669529663687f;
    float* ETs = ET + (size_t)slab * M_ * M_;
    #pragma unroll
    for (int d = 0; d < 32; d++)
        ETs[(size_t)(h * 32 + d) * M_ + tid] = scale * acc3[d];
}

// ============================================================
// 128x128 NT fp32 GEMM, f32x2, 8x8/thread, DOUBLE-BUFFERED.
//   mode 0: C = acc * e1[c] + e2[r,c]        (s2)
//   mode 1: C = gelu(acc + e1[c])            (fc1)
//   mode 2: C = acc + e1[c] + e2[r,c]        (fc2 + residual)
// ============================================================
__global__ void __launch_bounds__(256) gemm128(
    const float* __restrict__ Ab, int lda, long aStride,
    const float* __restrict__ Bb, int ldb, long bStride,
    float* __restrict__ Cb, int ldc, long cStride,
    int K, int Rlim, int mode,
    const float* __restrict__ e1,
    const float* __restrict__ e2, long e2Stride)
{
    int slab = blockIdx.z;
    const float* A = Ab + (size_t)slab * aStride;
    const float* B = Bb + (size_t)slab * bStride;
    float*       C = Cb + (size_t)slab * cStride;
    const float* E2 = e2 ? (e2 + (size_t)slab * e2Stride) : (const float*)0;

    int rowBase = blockIdx.x * 128;
    int colBase = blockIdx.y * 128;

    __shared__ float As[2][16][128], Bs[2][16][128];  // 32 KB
    int tid = threadIdx.x;
    int ldRow = tid >> 1;            // 0..127
    int ldK   = (tid & 1) << 3;      // 0 or 8
    int tx = tid & 15, ty = tid >> 4;
    int tx4 = tx << 2, ty4 = ty << 2;

    const float* Arow = A + (size_t)(rowBase + ldRow) * lda + ldK;
    const float* Brow = B + (size_t)(colBase + ldRow) * ldb + ldK;
    bool aValid = (rowBase + ldRow) < Rlim;

    const int NT = K >> 4;

    // preload tile 0
    {
        float4 av0, av1;
        if (aValid) { av0 = *(const float4*)Arow; av1 = *(const float4*)(Arow + 4); }
        else        { av0 = make_float4(0.f,0.f,0.f,0.f); av1 = av0; }
        float4 bv0 = *(const float4*)Brow;
        float4 bv1 = *(const float4*)(Brow + 4);
        As[0][ldK+0][ldRow]=av0.x; As[0][ldK+1][ldRow]=av0.y;
        As[0][ldK+2][ldRow]=av0.z; As[0][ldK+3][ldRow]=av0.w;
        As[0][ldK+4][ldRow]=av1.x; As[0][ldK+5][ldRow]=av1.y;
        As[0][ldK+6][ldRow]=av1.z; As[0][ldK+7][ldRow]=av1.w;
        Bs[0][ldK+0][ldRow]=bv0.x; Bs[0][ldK+1][ldRow]=bv0.y;
        Bs[0][ldK+2][ldRow]=bv0.z; Bs[0][ldK+3][ldRow]=bv0.w;
        Bs[0][ldK+4][ldRow]=bv1.x; Bs[0][ldK+5][ldRow]=bv1.y;
        Bs[0][ldK+6][ldRow]=bv1.z; Bs[0][ldK+7][ldRow]=bv1.w;
    }
    __syncthreads();

    u64 acc[8][4] = {};
    for (int it = 0; it < NT; it++) {
        int cur = it & 1;
        bool more = (it + 1 < NT);
        float4 nav0, nav1, nbv0, nbv1;
        if (more) {
            int k0 = (it + 1) << 4;
            if (aValid) { nav0 = *(const float4*)(Arow + k0); nav1 = *(const float4*)(Arow + k0 + 4); }
            else        { nav0 = make_float4(0.f,0.f,0.f,0.f); nav1 = nav0; }
            nbv0 = *(const float4*)(Brow + k0);
            nbv1 = *(const float4*)(Brow + k0 + 4);
        }

        #pragma unroll
        for (int k = 0; k < 16; k++) {
            float4 a0 = *(const float4*)&As[cur][k][ty4];
            float4 a1 = *(const float4*)&As[cur][k][ty4 + 64];
            ulonglong2 b0 = *(const ulonglong2*)&Bs[cur][k][tx4];
            ulonglong2 b1 = *(const ulonglong2*)&Bs[cur][k][tx4 + 64];
            u64 a2;
            a2 = dup2(a0.x); fma2(acc[0][0],a2,b0.x); fma2(acc[0][1],a2,b0.y); fma2(acc[0][2],a2,b1.x); fma2(acc[0][3],a2,b1.y);
            a2 = dup2(a0.y); fma2(acc[1][0],a2,b0.x); fma2(acc[1][1],a2,b0.y); fma2(acc[1][2],a2,b1.x); fma2(acc[1][3],a2,b1.y);
            a2 = dup2(a0.z); fma2(acc[2][0],a2,b0.x); fma2(acc[2][1],a2,b0.y); fma2(acc[2][2],a2,b1.x); fma2(acc[2][3],a2,b1.y);
            a2 = dup2(a0.w); fma2(acc[3][0],a2,b0.x); fma2(acc[3][1],a2,b0.y); fma2(acc[3][2],a2,b1.x); fma2(acc[3][3],a2,b1.y);
            a2 = dup2(a1.x); fma2(acc[4][0],a2,b0.x); fma2(acc[4][1],a2,b0.y); fma2(acc[4][2],a2,b1.x); fma2(acc[4][3],a2,b1.y);
            a2 = dup2(a1.y); fma2(acc[5][0],a2,b0.x); fma2(acc[5][1],a2,b0.y); fma2(acc[5][2],a2,b1.x); fma2(acc[5][3],a2,b1.y);
            a2 = dup2(a1.z); fma2(acc[6][0],a2,b0.x); fma2(acc[6][1],a2,b0.y); fma2(acc[6][2],a2,b1.x); fma2(acc[6][3],a2,b1.y);
            a2 = dup2(a1.w); fma2(acc[7][0],a2,b0.x); fma2(acc[7][1],a2,b0.y); fma2(acc[7][2],a2,b1.x); fma2(acc[7][3],a2,b1.y);
        }

        if (more) {
            int nxt = cur ^ 1;
            As[nxt][ldK+0][ldRow]=nav0.x; As[nxt][ldK+1][ldRow]=nav0.y;
            As[nxt][ldK+2][ldRow]=nav0.z; As[nxt][ldK+3][ldRow]=nav0.w;
            As[nxt][ldK+4][ldRow]=nav1.x; As[nxt][ldK+5][ldRow]=nav1.y;
            As[nxt][ldK+6][ldRow]=nav1.z; As[nxt][ldK+7][ldRow]=nav1.w;
            Bs[nxt][ldK+0][ldRow]=nbv0.x; Bs[nxt][ldK+1][ldRow]=nbv0.y;
            Bs[nxt][ldK+2][ldRow]=nbv0.z; Bs[nxt][ldK+3][ldRow]=nbv0.w;
            Bs[nxt][ldK+4][ldRow]=nbv1.x; Bs[nxt][ldK+5][ldRow]=nbv1.y;
            Bs[nxt][ldK+6][ldRow]=nbv1.z; Bs[nxt][ldK+7][ldRow]=nbv1.w;
        }
        __syncthreads();
    }

    #pragma unroll
    for (int i = 0; i < 8; i++) {
        int r = rowBase + ty4 + (i & 3) + ((i >> 2) << 6);
        if (r >= Rlim) continue;
        #pragma unroll
        for (int j2 = 0; j2 < 4; j2++) {
            int c = colBase + tx4 + ((j2 & 1) << 1) + ((j2 >> 1) << 6);
            float2 v = unpack2(acc[i][j2]);
            size_t idx = (size_t)r * ldc + c;
            if (mode == 0) {
                v.x = v.x * e1[c]     + E2[idx];
                v.y = v.y * e1[c + 1] + E2[idx + 1];
            } else if (mode == 1) {
                v.x += e1[c];
                v.y += e1[c + 1];
                v.x = 0.5f * v.x * (1.0f + erff(v.x * 0.7071067811865475f));
                v.y = 0.5f * v.y * (1.0f + erff(v.y * 0.7071067811865475f));
            } else {
                v.x = v.x + e1[c]     + E2[idx];
                v.y = v.y + e1[c + 1] + E2[idx + 1];
            }
            *(float2*)(C + idx) = v;
        }
    }
}

// ============================================================
// Launch
// ============================================================
extern "C" void kernel_launch(void* const* d_in, const int* in_sizes, int n_in,
                              void* d_out, int out_size)
{
    (void)in_sizes; (void)n_in; (void)out_size;
    const float* savespace = (const float*)d_in[1];
    const float* Wqkv      = (const float*)d_in[2];
    const float* Wo        = (const float*)d_in[3];
    const float* ln1_g     = (const float*)d_in[4];
    const float* ln1_b     = (const float*)d_in[5];
    const float* ln2_g     = (const float*)d_in[6];
    const float* ln2_b     = (const float*)d_in[7];
    const float* fc1_w     = (const float*)d_in[8];
    const float* fc1_b     = (const float*)d_in[9];
    const float* fc2_w     = (const float*)d_in[10];
    const float* fc2_b     = (const float*)d_in[11];
    float* out = (float*)d_out;

    float *p_sln, *p_s2, *p_hln, *p_h1, *p_G, *p_T, *p_ET, *p_ws;
    cudaGetSymbolAddress((void**)&p_sln, g_sln);
    cudaGetSymbolAddress((void**)&p_s2,  g_s2);
    cudaGetSymbolAddress((void**)&p_hln, g_hln);
    cudaGetSymbolAddress((void**)&p_h1,  g_h1);
    cudaGetSymbolAddress((void**)&p_G,   g_G);
    cudaGetSymbolAddress((void**)&p_T,   g_T);
    cudaGetSymbolAddress((void**)&p_ET,  g_ET);
    cudaGetSymbolAddress((void**)&p_ws,  g_wosum);

    const long SLAB = (long)J_ * M_;
    const long MM   = (long)M_ * M_;

    // 1) layernorm1
    ln_kernel<<<RTOT, 256>>>(savespace, ln1_g, ln1_b, p_sln);
    // 2) Gram per slab
    gram_kernel<<<dim3(4, 4, NSLAB), 256>>>(p_sln, p_G);
    // 3) Wo row sums
    rowsum_kernel<<<1, 256>>>(Wo, p_ws);
    // 4) T = G @ Wv_full^T per slab
    gemm64<<<dim3(4, 4, NSLAB), 256>>>(
        p_G, M_, MM,  Wqkv + 2 * H_ * DH_ * M_, M_, 0,  p_T, M_, MM, M_);
    // 5) finish ET per (head, slab)
    assemble2_kernel<<<dim3(H_, NSLAB), 256>>>(Wqkv, p_T, p_ET);
    // 6) s2 = wosum * (s_ln @ E) + savespace
    gemm128<<<dim3(9, 2, NSLAB), 256>>>(
        p_sln, M_, SLAB,  p_ET, M_, MM,  p_s2, M_, SLAB,
        M_, J_, 0, p_ws, savespace, SLAB);
    // 7) layernorm2
    ln_kernel<<<RTOT, 256>>>(p_s2, ln2_g, ln2_b, p_hln);
    // 8) h1 = gelu(hln @ fc1_w^T + b1)
    gemm128<<<dim3(129, 8, 1), 256>>>(
        p_hln, M_, 0,  fc1_w, M_, 0,  p_h1, FF_, 0,
        M_, RTOT, 1, fc1_b, (const float*)0, 0);
    // 9) out = h1 @ fc2_w^T + b2 + s2
    gemm128<<<dim3(129, 2, 1), 256>>>(
        p_h1, FF_, 0,  fc2_w, FF_, 0,  out, M_, 0,
        FF_, RTOT, 2, fc2_b, p_s2, 0);
}

// round 6
// speedup vs baseline: 1.4917x; 1.0460x over previous
#include <cuda_runtime.h>
#include <math.h>
#include <cstdint>

// Shapes (fixed by the problem)
#define B_    2
#define I_    8
#define J_    1025
#define M_    256
#define H_    8
#define DH_   32
#define NSLAB 16              // B_*I_
#define RTOT  (NSLAB * J_)    // 16400
#define FF_   1024            // 4*M

typedef unsigned long long u64;

// ---- scratch (static __device__ arrays; no runtime allocation) ----
__device__ float g_sln[RTOT * M_];
__device__ float g_s2 [RTOT * M_];
__device__ float g_hln[RTOT * M_];
__device__ float g_h1 [(size_t)RTOT * FF_];
__device__ float g_G  [NSLAB * M_ * M_];
__device__ float g_T  [NSLAB * M_ * M_];
__device__ float g_ET [NSLAB * M_ * M_];
__device__ float g_wosum[M_];

// ---- f32x2 packed-FMA helpers ----
__device__ __forceinline__ u64 dup2(float x) {
    u64 r; asm("mov.b64 %0, {%1,%1};" : "=l"(r) : "f"(x)); return r;
}
__device__ __forceinline__ void fma2(u64& d, u64 a, u64 b) {
    asm("fma.rn.f32x2 %0, %1, %2, %0;" : "+l"(d) : "l"(a), "l"(b));
}
__device__ __forceinline__ float2 unpack2(u64 v) {
    float2 r; asm("mov.b64 {%0,%1}, %2;" : "=f"(r.x), "=f"(r.y) : "l"(v)); return r;
}

// ---- tf32 mma helpers ----
__device__ __forceinline__ uint32_t f2tf32(float x) {
    uint32_t r; asm("cvt.rna.tf32.f32 %0, %1;" : "=r"(r) : "f"(x)); return r;
}
__device__ __forceinline__ void mma_tf32(float* c,
    uint32_t a0, uint32_t a1, uint32_t a2, uint32_t a3,
    uint32_t b0, uint32_t b1)
{
    asm("mma.sync.aligned.m16n8k8.row.col.f32.tf32.tf32.f32 "
        "{%0,%1,%2,%3}, {%4,%5,%6,%7}, {%8,%9}, {%0,%1,%2,%3};"
        : "+f"(c[0]), "+f"(c[1]), "+f"(c[2]), "+f"(c[3])
        : "r"(a0), "r"(a1), "r"(a2), "r"(a3), "r"(b0), "r"(b1));
}

// ============================================================
// LayerNorm over last dim M_=256, one block (256 thr) per row
// ============================================================
__global__ void ln_kernel(const float* __restrict__ x,
                          const float* __restrict__ g,
                          const float* __restrict__ b,
                          float* __restrict__ out)
{
    int row = blockIdx.x;
    const float* xr = x + (size_t)row * M_;
    int t = threadIdx.x;
    float v = xr[t];

    __shared__ float sm[8];
    float s = v;
    #pragma unroll
    for (int o = 16; o > 0; o >>= 1) s += __shfl_xor_sync(0xffffffffu, s, o);
    if ((t & 31) == 0) sm[t >> 5] = s;
    __syncthreads();
    float mean = 0.f;
    #pragma unroll
    for (int i = 0; i < 8; i++) mean += sm[i];
    mean *= (1.0f / M_);
    __syncthreads();
    float d = v - mean;
    float q = d * d;
    #pragma unroll
    for (int o = 16; o > 0; o >>= 1) q += __shfl_xor_sync(0xffffffffu, q, o);
    if ((t & 31) == 0) sm[t >> 5] = q;
    __syncthreads();
    float var = 0.f;
    #pragma unroll
    for (int i = 0; i < 8; i++) var += sm[i];
    var *= (1.0f / M_);

    out[(size_t)row * M_ + t] = d * rsqrtf(var + 1e-5f) * g[t] + b[t];
}

// ============================================================
// Wo row sums
// ============================================================
__global__ void rowsum_kernel(const float* __restrict__ Wo, float* __restrict__ ws)
{
    int n = threadIdx.x;
    float s = 0.f;
    for (int m = 0; m < M_; m++) s += Wo[(size_t)n * M_ + m];
    ws[n] = s;
}

// ============================================================
// Gram: G = S^T S per slab, symmetry + f32x2 + double buffer
// ============================================================
__global__ void __launch_bounds__(256) gram_kernel(const float* __restrict__ sln,
                                                   float* __restrict__ G)
{
    if (blockIdx.y < blockIdx.x) return;
    int slab = blockIdx.z;
    const float* A = sln + (size_t)slab * J_ * M_;
    int p0 = blockIdx.x * 64, q0 = blockIdx.y * 64;

    __shared__ float As[2][16][64], Bs[2][16][64];
    int tid = threadIdx.x;
    int jj = tid >> 4;
    int cq = (tid & 15) << 2;
    int tx = tid & 15, ty = tid >> 4;

    const int NT = (J_ + 15) / 16;   // 65

    float4 av, bv;
    {
        int j = jj;
        if (j < J_) {
            av = *(const float4*)(A + (size_t)j * M_ + p0 + cq);
            bv = *(const float4*)(A + (size_t)j * M_ + q0 + cq);
        } else { av = make_float4(0.f,0.f,0.f,0.f); bv = av; }
    }
    *(float4*)&As[0][jj][cq] = av;
    *(float4*)&Bs[0][jj][cq] = bv;
    __syncthreads();

    u64 acc[4][2] = {};
    for (int it = 0; it < NT; it++) {
        int cur = it & 1;
        float4 nav, nbv;
        bool more = (it + 1 < NT);
        if (more) {
            int j = (it + 1) * 16 + jj;
            if (j < J_) {
                nav = *(const float4*)(A + (size_t)j * M_ + p0 + cq);
                nbv = *(const float4*)(A + (size_t)j * M_ + q0 + cq);
            } else { nav = make_float4(0.f,0.f,0.f,0.f); nbv = nav; }
        }
        #pragma unroll
        for (int k = 0; k < 16; k++) {
            float4 a = *(const float4*)&As[cur][k][ty << 2];
            ulonglong2 b = *(const ulonglong2*)&Bs[cur][k][tx << 2];
            u64 a2;
            a2 = dup2(a.x); fma2(acc[0][0], a2, b.x); fma2(acc[0][1], a2, b.y);
            a2 = dup2(a.y); fma2(acc[1][0], a2, b.x); fma2(acc[1][1], a2, b.y);
            a2 = dup2(a.z); fma2(acc[2][0], a2, b.x); fma2(acc[2][1], a2, b.y);
            a2 = dup2(a.w); fma2(acc[3][0], a2, b.x); fma2(acc[3][1], a2, b.y);
        }
        if (more) {
            *(float4*)&As[cur ^ 1][jj][cq] = nav;
            *(float4*)&Bs[cur ^ 1][jj][cq] = nbv;
        }
        __syncthreads();
    }
    float* Gs = G + (size_t)slab * M_ * M_;
    #pragma unroll
    for (int i = 0; i < 4; i++) {
        int p = p0 + (ty << 2) + i;
        #pragma unroll
        for (int j2 = 0; j2 < 2; j2++) {
            float2 v = unpack2(acc[i][j2]);
            int q = q0 + (tx << 2) + j2 * 2;
            Gs[(size_t)p * M_ + q]     = v.x;
            Gs[(size_t)p * M_ + q + 1] = v.y;
            Gs[(size_t)q * M_ + p]       = v.x;
            Gs[(size_t)(q + 1) * M_ + p] = v.y;
        }
    }
}

// ============================================================
// 64x64 NT GEMM (T = G @ Wv^T)
// ============================================================
__global__ void __launch_bounds__(256) gemm64(
    const float* __restrict__ Ab, int lda, long aStride,
    const float* __restrict__ Bb, int ldb, long bStride,
    float* __restrict__ Cb, int ldc, long cStride, int K)
{
    int slab = blockIdx.z;
    const float* A = Ab + (size_t)slab * aStride;
    const float* B = Bb + (size_t)slab * bStride;
    float*       C = Cb + (size_t)slab * cStride;

    int rowBase = blockIdx.x * 64;
    int colBase = blockIdx.y * 64;

    __shared__ float As[16][64], Bs[16][64];
    int tid = threadIdx.x;
    int lm = tid >> 2;
    int lk = (tid & 3) << 2;
    int tx = tid & 15, ty = tid >> 4;

    u64 acc[4][2] = {};
    for (int k0 = 0; k0 < K; k0 += 16) {
        float4 av = *(const float4*)(A + (size_t)(rowBase + lm) * lda + k0 + lk);
        As[lk + 0][lm] = av.x; As[lk + 1][lm] = av.y;
        As[lk + 2][lm] = av.z; As[lk + 3][lm] = av.w;
        float4 bv = *(const float4*)(B + (size_t)(colBase + lm) * ldb + k0 + lk);
        Bs[lk + 0][lm] = bv.x; Bs[lk + 1][lm] = bv.y;
        Bs[lk + 2][lm] = bv.z; Bs[lk + 3][lm] = bv.w;
        __syncthreads();
        #pragma unroll
        for (int k = 0; k < 16; k++) {
            float4 a = *(const float4*)&As[k][ty << 2];
            ulonglong2 b = *(const ulonglong2*)&Bs[k][tx << 2];
            u64 a2;
            a2 = dup2(a.x); fma2(acc[0][0], a2, b.x); fma2(acc[0][1], a2, b.y);
            a2 = dup2(a.y); fma2(acc[1][0], a2, b.x); fma2(acc[1][1], a2, b.y);
            a2 = dup2(a.z); fma2(acc[2][0], a2, b.x); fma2(acc[2][1], a2, b.y);
            a2 = dup2(a.w); fma2(acc[3][0], a2, b.x); fma2(acc[3][1], a2, b.y);
        }
        __syncthreads();
    }
    #pragma unroll
    for (int i = 0; i < 4; i++) {
        int r = rowBase + (ty << 2) + i;
        #pragma unroll
        for (int j2 = 0; j2 < 2; j2++) {
            int c = colBase + (tx << 2) + j2 * 2;
            float2 v = unpack2(acc[i][j2]);
            *(float2*)(C + (size_t)r * ldc + c) = v;
        }
    }
}

// ============================================================
// Small per-(head,slab) finisher
// ============================================================
__global__ void __launch_bounds__(256) assemble2_kernel(const float* __restrict__ Wqkv,
                                                        const float* __restrict__ T,
                                                        float* __restrict__ ET)
{
    int h = blockIdx.x;
    int slab = blockIdx.y;
    const float* Ts = T + (size_t)slab * M_ * M_;
    const float* Wq = Wqkv + (size_t)(0 * H_ + h) * DH_ * M_;
    const float* Wk = Wqkv + (size_t)(1 * H_ + h) * DH_ * M_;

    __shared__ float sT[256][33];
    __shared__ float ktv[32][33];
    int tid = threadIdx.x;

    {
        int m = tid >> 5, d = tid & 31;
        #pragma unroll
        for (int pass = 0; pass < 32; pass++) {
            int mm = pass * 8 + m;
            sT[mm][d] = Ts[(size_t)mm * M_ + h * 32 + d];
        }
    }
    __syncthreads();

    {
        int d  = tid & 31;
        int e0 = (tid >> 5) << 2;
        float acc4[4] = {0.f, 0.f, 0.f, 0.f};
        for (int m = 0; m < 256; m++) {
            float t = sT[m][d];
            #pragma unroll
            for (int ee = 0; ee < 4; ee++)
                acc4[ee] = fmaf(Wk[(size_t)(e0 + ee) * M_ + m], t, acc4[ee]);
        }
        #pragma unroll
        for (int ee = 0; ee < 4; ee++)
            ktv[e0 + ee][d] = acc4[ee];
    }
    __syncthreads();

    float acc3[32];
    #pragma unroll
    for (int d = 0; d < 32; d++) acc3[d] = 0.f;
    for (int e2 = 0; e2 < 32; e2++) {
        float w = Wq[(size_t)e2 * M_ + tid];
        #pragma unroll
        for (int d = 0; d < 32; d++) acc3[d] = fmaf(w, ktv[e2][d], acc3[d]);
    }
    const float scale = 0.17677669529663687f;
    float* ETs = ET + (size_t)slab * M_ * M_;
    #pragma unroll
    for (int d = 0; d < 32; d++)
        ETs[(size_t)(h * 32 + d) * M_ + tid] = scale * acc3[d];
}

// ============================================================
// 128x128 NT fp32 GEMM, f32x2, double-buffered (s2 only).
//   C = acc * e1[c] + e2[r,c]
// ============================================================
__global__ void __launch_bounds__(256) gemm128(
    const float* __restrict__ Ab, int lda, long aStride,
    const float* __restrict__ Bb, int ldb, long bStride,
    float* __restrict__ Cb, int ldc, long cStride,
    int K, int Rlim,
    const float* __restrict__ e1,
    const float* __restrict__ e2, long e2Stride)
{
    int slab = blockIdx.z;
    const float* A = Ab + (size_t)slab * aStride;
    const float* B = Bb + (size_t)slab * bStride;
    float*       C = Cb + (size_t)slab * cStride;
    const float* E2 = e2 + (size_t)slab * e2Stride;

    int rowBase = blockIdx.x * 128;
    int colBase = blockIdx.y * 128;

    __shared__ float As[2][16][128], Bs[2][16][128];
    int tid = threadIdx.x;
    int ldRow = tid >> 1;
    int ldK   = (tid & 1) << 3;
    int tx = tid & 15, ty = tid >> 4;
    int tx4 = tx << 2, ty4 = ty << 2;

    const float* Arow = A + (size_t)(rowBase + ldRow) * lda + ldK;
    const float* Brow = B + (size_t)(colBase + ldRow) * ldb + ldK;
    bool aValid = (rowBase + ldRow) < Rlim;

    const int NT = K >> 4;

    {
        float4 av0, av1;
        if (aValid) { av0 = *(const float4*)Arow; av1 = *(const float4*)(Arow + 4); }
        else        { av0 = make_float4(0.f,0.f,0.f,0.f); av1 = av0; }
        float4 bv0 = *(const float4*)Brow;
        float4 bv1 = *(const float4*)(Brow + 4);
        As[0][ldK+0][ldRow]=av0.x; As[0][ldK+1][ldRow]=av0.y;
        As[0][ldK+2][ldRow]=av0.z; As[0][ldK+3][ldRow]=av0.w;
        As[0][ldK+4][ldRow]=av1.x; As[0][ldK+5][ldRow]=av1.y;
        As[0][ldK+6][ldRow]=av1.z; As[0][ldK+7][ldRow]=av1.w;
        Bs[0][ldK+0][ldRow]=bv0.x; Bs[0][ldK+1][ldRow]=bv0.y;
        Bs[0][ldK+2][ldRow]=bv0.z; Bs[0][ldK+3][ldRow]=bv0.w;
        Bs[0][ldK+4][ldRow]=bv1.x; Bs[0][ldK+5][ldRow]=bv1.y;
        Bs[0][ldK+6][ldRow]=bv1.z; Bs[0][ldK+7][ldRow]=bv1.w;
    }
    __syncthreads();

    u64 acc[8][4] = {};
    for (int it = 0; it < NT; it++) {
        int cur = it & 1;
        bool more = (it + 1 < NT);
        float4 nav0, nav1, nbv0, nbv1;
        if (more) {
            int k0 = (it + 1) << 4;
            if (aValid) { nav0 = *(const float4*)(Arow + k0); nav1 = *(const float4*)(Arow + k0 + 4); }
            else        { nav0 = make_float4(0.f,0.f,0.f,0.f); nav1 = nav0; }
            nbv0 = *(const float4*)(Brow + k0);
            nbv1 = *(const float4*)(Brow + k0 + 4);
        }

        #pragma unroll
        for (int k = 0; k < 16; k++) {
            float4 a0 = *(const float4*)&As[cur][k][ty4];
            float4 a1 = *(const float4*)&As[cur][k][ty4 + 64];
            ulonglong2 b0 = *(const ulonglong2*)&Bs[cur][k][tx4];
            ulonglong2 b1 = *(const ulonglong2*)&Bs[cur][k][tx4 + 64];
            u64 a2;
            a2 = dup2(a0.x); fma2(acc[0][0],a2,b0.x); fma2(acc[0][1],a2,b0.y); fma2(acc[0][2],a2,b1.x); fma2(acc[0][3],a2,b1.y);
            a2 = dup2(a0.y); fma2(acc[1][0],a2,b0.x); fma2(acc[1][1],a2,b0.y); fma2(acc[1][2],a2,b1.x); fma2(acc[1][3],a2,b1.y);
            a2 = dup2(a0.z); fma2(acc[2][0],a2,b0.x); fma2(acc[2][1],a2,b0.y); fma2(acc[2][2],a2,b1.x); fma2(acc[2][3],a2,b1.y);
            a2 = dup2(a0.w); fma2(acc[3][0],a2,b0.x); fma2(acc[3][1],a2,b0.y); fma2(acc[3][2],a2,b1.x); fma2(acc[3][3],a2,b1.y);
            a2 = dup2(a1.x); fma2(acc[4][0],a2,b0.x); fma2(acc[4][1],a2,b0.y); fma2(acc[4][2],a2,b1.x); fma2(acc[4][3],a2,b1.y);
            a2 = dup2(a1.y); fma2(acc[5][0],a2,b0.x); fma2(acc[5][1],a2,b0.y); fma2(acc[5][2],a2,b1.x); fma2(acc[5][3],a2,b1.y);
            a2 = dup2(a1.z); fma2(acc[6][0],a2,b0.x); fma2(acc[6][1],a2,b0.y); fma2(acc[6][2],a2,b1.x); fma2(acc[6][3],a2,b1.y);
            a2 = dup2(a1.w); fma2(acc[7][0],a2,b0.x); fma2(acc[7][1],a2,b0.y); fma2(acc[7][2],a2,b1.x); fma2(acc[7][3],a2,b1.y);
        }

        if (more) {
            int nxt = cur ^ 1;
            As[nxt][ldK+0][ldRow]=nav0.x; As[nxt][ldK+1][ldRow]=nav0.y;
            As[nxt][ldK+2][ldRow]=nav0.z; As[nxt][ldK+3][ldRow]=nav0.w;
            As[nxt][ldK+4][ldRow]=nav1.x; As[nxt][ldK+5][ldRow]=nav1.y;
            As[nxt][ldK+6][ldRow]=nav1.z; As[nxt][ldK+7][ldRow]=nav1.w;
            Bs[nxt][ldK+0][ldRow]=nbv0.x; Bs[nxt][ldK+1][ldRow]=nbv0.y;
            Bs[nxt][ldK+2][ldRow]=nbv0.z; Bs[nxt][ldK+3][ldRow]=nbv0.w;
            Bs[nxt][ldK+4][ldRow]=nbv1.x; Bs[nxt][ldK+5][ldRow]=nbv1.y;
            Bs[nxt][ldK+6][ldRow]=nbv1.z; Bs[nxt][ldK+7][ldRow]=nbv1.w;
        }
        __syncthreads();
    }

    #pragma unroll
    for (int i = 0; i < 8; i++) {
        int r = rowBase + ty4 + (i & 3) + ((i >> 2) << 6);
        if (r >= Rlim) continue;
        #pragma unroll
        for (int j2 = 0; j2 < 4; j2++) {
            int c = colBase + tx4 + ((j2 & 1) << 1) + ((j2 >> 1) << 6);
            float2 v = unpack2(acc[i][j2]);
            size_t idx = (size_t)r * ldc + c;
            v.x = v.x * e1[c]     + E2[idx];
            v.y = v.y * e1[c + 1] + E2[idx + 1];
            *(float2*)(C + idx) = v;
        }
    }
}

// ============================================================
// 3xTF32 tensor-core NT GEMM: C[r,c] = sum_k A[r,k]*B[c,k]
// 128x128 CTA, 8 warps (2x4), 64x32 per warp, m16n8k8.
//   mode 1: C = gelu(acc + bias[c])
//   mode 2: C = acc + bias[c] + resid[r,c]
// K multiple of 16; cols multiple of 128; rows guarded.
// ============================================================
#define BKP 20   // padded smem row stride (floats) -> conflict-free frags
__global__ void __launch_bounds__(256) tf32_gemm(
    const float* __restrict__ A, int lda,
    const float* __restrict__ B, int ldb,
    float* __restrict__ C, int ldc,
    int K, int Rlim, int mode,
    const float* __restrict__ bias,
    const float* __restrict__ resid)
{
    __shared__ float As[2][128 * BKP], Bs[2][128 * BKP];
    int tid = threadIdx.x;
    int rowBase = blockIdx.x * 128, colBase = blockIdx.y * 128;

    int ldRow = tid >> 1;            // 0..127
    int ldK   = (tid & 1) << 3;      // 0 or 8
    const float* Arow = A + (size_t)(rowBase + ldRow) * lda + ldK;
    const float* Brow = B + (size_t)(colBase + ldRow) * ldb + ldK;
    bool aValid = (rowBase + ldRow) < Rlim;

    int lane = tid & 31, warp = tid >> 5;
    int wRow = (warp >> 2) << 6;     // 0 or 64
    int wCol = (warp & 3) << 5;      // 0,32,64,96
    int g = lane >> 2, t = lane & 3;

    const int NT = K >> 4;

    // preload tile 0
    {
        float4 av0, av1;
        if (aValid) { av0 = *(const float4*)Arow; av1 = *(const float4*)(Arow + 4); }
        else        { av0 = make_float4(0.f,0.f,0.f,0.f); av1 = av0; }
        float4 bv0 = *(const float4*)Brow;
        float4 bv1 = *(const float4*)(Brow + 4);
        float* pa = &As[0][ldRow * BKP + ldK];
        pa[0]=av0.x; pa[1]=av0.y; pa[2]=av0.z; pa[3]=av0.w;
        pa[4]=av1.x; pa[5]=av1.y; pa[6]=av1.z; pa[7]=av1.w;
        float* pb = &Bs[0][ldRow * BKP + ldK];
        pb[0]=bv0.x; pb[1]=bv0.y; pb[2]=bv0.z; pb[3]=bv0.w;
        pb[4]=bv1.x; pb[5]=bv1.y; pb[6]=bv1.z; pb[7]=bv1.w;
    }
    __syncthreads();

    float acc[4][4][4];
    #pragma unroll
    for (int i = 0; i < 4; i++)
        #pragma unroll
        for (int j = 0; j < 4; j++)
            #pragma unroll
            for (int q = 0; q < 4; q++) acc[i][j][q] = 0.f;

    for (int it = 0; it < NT; it++) {
        int cur = it & 1;
        bool more = (it + 1 < NT);
        float4 nav0, nav1, nbv0, nbv1;
        if (more) {
            int k0 = (it + 1) << 4;
            if (aValid) { nav0 = *(const float4*)(Arow + k0); nav1 = *(const float4*)(Arow + k0 + 4); }
            else        { nav0 = make_float4(0.f,0.f,0.f,0.f); nav1 = nav0; }
            nbv0 = *(const float4*)(Brow + k0);
            nbv1 = *(const float4*)(Brow + k0 + 4);
        }

        const float* sa = As[cur];
        const float* sb = Bs[cur];
        #pragma unroll
        for (int ks = 0; ks < 2; ks++) {
            int kk = (ks << 3) + t;
            // load + split A fragments (4 m-blocks)
            uint32_t ahi[4][4], alo[4][4];
            #pragma unroll
            for (int mb = 0; mb < 4; mb++) {
                int rb = wRow + (mb << 4);
                float x0 = sa[(rb + g)     * BKP + kk];
                float x1 = sa[(rb + g + 8) * BKP + kk];
                float x2 = sa[(rb + g)     * BKP + kk + 4];
                float x3 = sa[(rb + g + 8) * BKP + kk + 4];
                ahi[mb][0] = f2tf32(x0); alo[mb][0] = __float_as_uint(x0 - __uint_as_float(ahi[mb][0]));
                ahi[mb][1] = f2tf32(x1); alo[mb][1] = __float_as_uint(x1 - __uint_as_float(ahi[mb][1]));
                ahi[mb][2] = f2tf32(x2); alo[mb][2] = __float_as_uint(x2 - __uint_as_float(ahi[mb][2]));
                ahi[mb][3] = f2tf32(x3); alo[mb][3] = __float_as_uint(x3 - __uint_as_float(ahi[mb][3]));
            }
            // load + split B fragments (4 n-blocks)
            uint32_t bhi[4][2], blo[4][2];
            #pragma unroll
            for (int nb = 0; nb < 4; nb++) {
                int cb = wCol + (nb << 3);
                float y0 = sb[(cb + g) * BKP + kk];
                float y1 = sb[(cb + g) * BKP + kk + 4];
                bhi[nb][0] = f2tf32(y0); blo[nb][0] = __float_as_uint(y0 - __uint_as_float(bhi[nb][0]));
                bhi[nb][1] = f2tf32(y1); blo[nb][1] = __float_as_uint(y1 - __uint_as_float(bhi[nb][1]));
            }
            // 3 products: ah*bl, al*bh, ah*bh
            #pragma unroll
            for (int mb = 0; mb < 4; mb++)
                #pragma unroll
                for (int nb = 0; nb < 4; nb++)
                    mma_tf32(acc[mb][nb], ahi[mb][0], ahi[mb][1], ahi[mb][2], ahi[mb][3], blo[nb][0], blo[nb][1]);
            #pragma unroll
            for (int mb = 0; mb < 4; mb++)
                #pragma unroll
                for (int nb = 0; nb < 4; nb++)
                    mma_tf32(acc[mb][nb], alo[mb][0], alo[mb][1], alo[mb][2], alo[mb][3], bhi[nb][0], bhi[nb][1]);
            #pragma unroll
            for (int mb = 0; mb < 4; mb++)
                #pragma unroll
                for (int nb = 0; nb < 4; nb++)
                    mma_tf32(acc[mb][nb], ahi[mb][0], ahi[mb][1], ahi[mb][2], ahi[mb][3], bhi[nb][0], bhi[nb][1]);
        }

        if (more) {
            int nxt = cur ^ 1;
            float* pa = &As[nxt][ldRow * BKP + ldK];
            pa[0]=nav0.x; pa[1]=nav0.y; pa[2]=nav0.z; pa[3]=nav0.w;
            pa[4]=nav1.x; pa[5]=nav1.y; pa[6]=nav1.z; pa[7]=nav1.w;
            float* pb = &Bs[nxt][ldRow * BKP + ldK];
            pb[0]=nbv0.x; pb[1]=nbv0.y; pb[2]=nbv0.z; pb[3]=nbv0.w;
            pb[4]=nbv1.x; pb[5]=nbv1.y; pb[6]=nbv1.z; pb[7]=nbv1.w;
        }
        __syncthreads();
    }

    // epilogue
    const float inv_sqrt2 = 0.7071067811865475f;
    #pragma unroll
    for (int mb = 0; mb < 4; mb++) {
        int r0 = rowBase + wRow + (mb << 4) + g;
        #pragma unroll
        for (int half = 0; half < 2; half++) {
            int r = r0 + half * 8;
            if (r >= Rlim) continue;
            #pragma unroll
            for (int nb = 0; nb < 4; nb++) {
                int c = colBase + wCol + (nb << 3) + (t << 1);
                float vx = acc[mb][nb][half * 2 + 0];
                float vy = acc[mb][nb][half * 2 + 1];
                if (mode == 1) {
                    vx += bias[c];
                    vy += bias[c + 1];
                    vx = 0.5f * vx * (1.0f + erff(vx * inv_sqrt2));
                    vy = 0.5f * vy * (1.0f + erff(vy * inv_sqrt2));
                } else {
                    const float* rr = resid + (size_t)r * ldc + c;
                    vx += bias[c]     + rr[0];
                    vy += bias[c + 1] + rr[1];
                }
                *(float2*)(C + (size_t)r * ldc + c) = make_float2(vx, vy);
            }
        }
    }
}

// ============================================================
// Launch
// ============================================================
extern "C" void kernel_launch(void* const* d_in, const int* in_sizes, int n_in,
                              void* d_out, int out_size)
{
    (void)in_sizes; (void)n_in; (void)out_size;
    const float* savespace = (const float*)d_in[1];
    const float* Wqkv      = (const float*)d_in[2];
    const float* Wo        = (const float*)d_in[3];
    const float* ln1_g     = (const float*)d_in[4];
    const float* ln1_b     = (const float*)d_in[5];
    const float* ln2_g     = (const float*)d_in[6];
    const float* ln2_b     = (const float*)d_in[7];
    const float* fc1_w     = (const float*)d_in[8];
    const float* fc1_b     = (const float*)d_in[9];
    const float* fc2_w     = (const float*)d_in[10];
    const float* fc2_b     = (const float*)d_in[11];
    float* out = (float*)d_out;

    float *p_sln, *p_s2, *p_hln, *p_h1, *p_G, *p_T, *p_ET, *p_ws;
    cudaGetSymbolAddress((void**)&p_sln, g_sln);
    cudaGetSymbolAddress((void**)&p_s2,  g_s2);
    cudaGetSymbolAddress((void**)&p_hln, g_hln);
    cudaGetSymbolAddress((void**)&p_h1,  g_h1);
    cudaGetSymbolAddress((void**)&p_G,   g_G);
    cudaGetSymbolAddress((void**)&p_T,   g_T);
    cudaGetSymbolAddress((void**)&p_ET,  g_ET);
    cudaGetSymbolAddress((void**)&p_ws,  g_wosum);

    const long SLAB = (long)J_ * M_;
    const long MM   = (long)M_ * M_;

    // 1) layernorm1
    ln_kernel<<<RTOT, 256>>>(savespace, ln1_g, ln1_b, p_sln);
    // 2) Gram per slab
    gram_kernel<<<dim3(4, 4, NSLAB), 256>>>(p_sln, p_G);
    // 3) Wo row sums
    rowsum_kernel<<<1, 256>>>(Wo, p_ws);
    // 4) T = G @ Wv_full^T per slab
    gemm64<<<dim3(4, 4, NSLAB), 256>>>(
        p_G, M_, MM,  Wqkv + 2 * H_ * DH_ * M_, M_, 0,  p_T, M_, MM, M_);
    // 5) finish ET per (head, slab)
    assemble2_kernel<<<dim3(H_, NSLAB), 256>>>(Wqkv, p_T, p_ET);
    // 6) s2 = wosum * (s_ln @ E) + savespace
    gemm128<<<dim3(9, 2, NSLAB), 256>>>(
        p_sln, M_, SLAB,  p_ET, M_, MM,  p_s2, M_, SLAB,
        M_, J_, p_ws, savespace, SLAB);
    // 7) layernorm2
    ln_kernel<<<RTOT, 256>>>(p_s2, ln2_g, ln2_b, p_hln);
    // 8) h1 = gelu(hln @ fc1_w^T + b1)   [3xTF32 tensor cores]
    tf32_gemm<<<dim3(129, 8), 256>>>(
        p_hln, M_, fc1_w, M_, p_h1, FF_,
        M_, RTOT, 1, fc1_b, (const float*)0);
    // 9) out = h1 @ fc2_w^T + b2 + s2    [3xTF32 tensor cores]
    tf32_gemm<<<dim3(129, 2), 256>>>(
        p_h1, FF_, fc2_w, FF_, out, M_,
        FF_, RTOT, 2, fc2_b, p_s2);
}